// round 2
// baseline (speedup 1.0000x reference)
#include <cuda_runtime.h>

#define GROWS 1028
#define GCOLS 1028
#define NCELL (GROWS * GCOLS)

// Quad layout: g_q[r*GCOLS+c] holds the full 4x4 stencil anchored at (r,c):
// row[j] = coeffs[r+j, c..c+3].  64 bytes, 64B-aligned -> always within ONE
// 128B cache line. 1028*1028*64B = 67.6 MB (L2-resident).
struct __align__(64) Quad { float4 row[4]; };
__device__ Quad g_q[NCELL];

__global__ void expand_kernel(const float* __restrict__ coeffs) {
    int idx = blockIdx.x * blockDim.x + threadIdx.x;  // = cell*4 + j
    if (idx >= NCELL * 4) return;
    int j = idx & 3;
    int cell = idx >> 2;
    int r = cell / GCOLS;
    int c = cell - r * GCOLS;
    int rr = min(r + j, GROWS - 1);
    const float* row = coeffs + rr * GCOLS;
    float4 v;
    v.x = __ldg(row + c);
    v.y = __ldg(row + min(c + 1, GCOLS - 1));
    v.z = __ldg(row + min(c + 2, GCOLS - 1));
    v.w = __ldg(row + min(c + 3, GCOLS - 1));
    reinterpret_cast<float4*>(g_q)[idx] = v;  // coalesced float4 stores
}

__global__ void __launch_bounds__(256) spline_kernel(
    const float2* __restrict__ x, float* __restrict__ out, int n)
{
    const int lane = threadIdx.x & 31;
    const int warpId = (blockIdx.x * blockDim.x + threadIdx.x) >> 5;
    const int p0 = warpId * 32;

    // Each lane owns one point's coords (coalesced 256B load per warp).
    int myIdx = p0 + lane;
    float2 p = (myIdx < n) ? __ldg(&x[myIdx]) : make_float2(2.0f, 2.0f);

    const int j = lane & 3;   // stencil row handled by this lane
    const int g = lane >> 2;  // point-group within the round (0..7)
    float myres = 0.0f;

    #pragma unroll
    for (int k = 0; k < 4; k++) {
        // This round: 4-lane group g processes point p0 + k*8 + g
        int src = k * 8 + g;
        float px = __shfl_sync(0xffffffffu, p.x, src);
        float py = __shfl_sync(0xffffffffu, p.y, src);

        float xn0 = px * 1024.0f - 0.5f;
        float xn1 = py * 1024.0f - 0.5f;
        bool valid = (xn0 > -2.0f) && (xn0 < 1024.0f) &&
                     (xn1 > -2.0f) && (xn1 < 1024.0f);

        float P0 = floorf(xn0), P1 = floorf(xn1);
        float t0 = xn0 - P0,    t1 = xn1 - P1;

        // Column weights (all 4, every lane)
        float o1 = 1.0f - t1, m1 = t1 - 1.0f;
        float w1a = o1 * o1 * o1;
        float w1b = (3.0f * t1 - 6.0f) * t1 * t1 + 4.0f;
        float w1c = -(3.0f * t1 + 3.0f) * m1 * m1 + 4.0f;
        float w1d = t1 * t1 * t1;

        // Row weight for this lane's j only (branchless selects)
        float o0 = 1.0f - t0, m0 = t0 - 1.0f;
        float w0j = (j == 0) ? o0 * o0 * o0
                  : (j == 1) ? (3.0f * t0 - 6.0f) * t0 * t0 + 4.0f
                  : (j == 2) ? -(3.0f * t0 + 3.0f) * m0 * m0 + 4.0f
                  :            t0 * t0 * t0;

        int r0 = (int)P0 + 1;
        int c0 = (int)P1 + 1;
        r0 = min(max(r0, 0), GROWS - 4);
        c0 = min(max(c0, 0), GCOLS - 4);

        // The 4 lanes of this group load 4 consecutive float4s of ONE 64B block.
        float4 v = __ldg(&g_q[r0 * GCOLS + c0].row[j]);

        float s = fmaf(v.x, w1a, fmaf(v.y, w1b, fmaf(v.z, w1c, v.w * w1d)));
        s *= w0j;
        // Butterfly reduce across the 4-lane group (all 4 lanes end with sum)
        s += __shfl_xor_sync(0xffffffffu, s, 1);
        s += __shfl_xor_sync(0xffffffffu, s, 2);
        s = valid ? s : 0.0f;

        // Gather round results so lane l ends owning point l's value.
        float r = __shfl_sync(0xffffffffu, s, (lane & 7) * 4);
        if ((lane >> 3) == k) myres = r;
    }

    if (myIdx < n) out[myIdx] = myres;
}

extern "C" void kernel_launch(void* const* d_in, const int* in_sizes, int n_in,
                              void* d_out, int out_size) {
    const float2* x = (const float2*)d_in[0];     // [N,2] float32
    const float* coeffs = (const float*)d_in[1];  // [1028,1028] float32
    float* out = (float*)d_out;                   // [N,1] float32
    int n = out_size;                             // 2097152

    int total = NCELL * 4;
    expand_kernel<<<(total + 255) / 256, 256>>>(coeffs);
    spline_kernel<<<(n + 255) / 256, 256>>>(x, out, n);
}